// round 10
// baseline (speedup 1.0000x reference)
#include <cuda_runtime.h>
#include <cstdint>

#define E_TOT   32768
#define N_NODES 2048
#define D       128
#define DF      32
#define DCAT    160
#define MAXED   64     // nodes per edge cap (mean ~10.2)
#define MAXNE   256    // edges per node cap (mean ~164)
#define XS      132    // x-tile stride: 16B-aligned rows for float4 LDS

// Scratch (__device__ globals: allocation-free rule)
__device__ float g_s [(size_t)E_TOT * D];
__device__ float g_cat[(size_t)E_TOT * D];     // agg = maskT@node - s
__device__ float g_node[(size_t)N_NODES * D];
__device__ int   g_edeg[E_TOT];
__device__ int   g_enode[(size_t)E_TOT * MAXED];
__device__ int   g_ncnt[N_NODES];
__device__ int   g_nlist[(size_t)N_NODES * MAXNE];
// Pre-transposed weights (k-major)
__device__ float g_w1mT[D * D];
__device__ float g_w2mT[D * D];
__device__ float g_w1aT[DCAT * D];
__device__ float g_w2aT[D * D];

__device__ __forceinline__ float lsig(float x) {
    return fminf(x, 0.0f) - log1pf(__expf(-fabsf(x)));
}

// Packed dual-FMA (sm_103a FFMA2)
__device__ __forceinline__ void ffma2(float2& d, const float2 a, const float2 b) {
    asm("fma.rn.f32x2 %0, %1, %2, %0;"
        : "+l"(*reinterpret_cast<unsigned long long*>(&d))
        : "l"(*reinterpret_cast<const unsigned long long*>(&a)),
          "l"(*reinterpret_cast<const unsigned long long*>(&b)));
}

__global__ void zero_kernel() {
    int i = blockIdx.x * blockDim.x + threadIdx.x;
    if (i < E_TOT) g_edeg[i] = 0;
    if (i < N_NODES) g_ncnt[i] = 0;
}

__global__ void wtrans_kernel(const float* __restrict__ W1m, const float* __restrict__ W2m,
                              const float* __restrict__ W1a, const float* __restrict__ W2a) {
    int i = blockIdx.x * blockDim.x + threadIdx.x;
    if (i < 16384) {
        int r = i >> 7, c = i & 127;
        g_w1mT[c * 128 + r] = W1m[i];
    } else if (i < 32768) {
        int j = i - 16384; int r = j >> 7, c = j & 127;
        g_w2mT[c * 128 + r] = W2m[j];
    } else if (i < 53248) {
        int j = i - 32768; int r = j / 160, c = j - r * 160;
        g_w1aT[c * 128 + r] = W1a[j];
    } else if (i < 69632) {
        int j = i - 53248; int r = j >> 7, c = j & 127;
        g_w2aT[c * 128 + r] = W2a[j];
    }
}

// ---------------------------------------------------------------------------
// 8x8 micro-tile GEMM step: 32B weights feed 64 MACs (0.5 B/MAC).
// ---------------------------------------------------------------------------
#define GEMM_K_STEP8(XK, WK, ACC)                                              \
    {                                                                          \
        const float4* _wkp = (WK);                                             \
        float4 _w0 = __ldg(_wkp), _w1 = __ldg(_wkp + 1);                       \
        const float4* _xp = reinterpret_cast<const float4*>(XK);               \
        float4 _xa = _xp[0], _xb = _xp[1];                                     \
        float2 _p0 = make_float2(_w0.x, _w0.y);                                \
        float2 _p1 = make_float2(_w0.z, _w0.w);                                \
        float2 _p2 = make_float2(_w1.x, _w1.y);                                \
        float2 _p3 = make_float2(_w1.z, _w1.w);                                \
        float _av[8] = {_xa.x, _xa.y, _xa.z, _xa.w, _xb.x, _xb.y, _xb.z, _xb.w};\
        _Pragma("unroll")                                                      \
        for (int _i = 0; _i < 8; ++_i) {                                       \
            float2 _ab = make_float2(_av[_i], _av[_i]);                        \
            ffma2(ACC[_i][0], _ab, _p0); ffma2(ACC[_i][1], _ab, _p1);          \
            ffma2(ACC[_i][2], _ab, _p2); ffma2(ACC[_i][3], _ab, _p3);          \
        }                                                                      \
    }

#define ACC_CLEAR8(ACC)                                                        \
    _Pragma("unroll") for (int i = 0; i < 8; ++i)                              \
    _Pragma("unroll") for (int j = 0; j < 4; ++j) ACC[i][j] = make_float2(0.f, 0.f);

// ---------------------------------------------------------------------------
// Fused memory MLP: g_s = ls( ls(state @ W1m^T + b1m) @ W2m^T )
// ---------------------------------------------------------------------------
__global__ void __launch_bounds__(256, 2) mem_mlp_kernel(const float* __restrict__ state,
                                                         const float* __restrict__ b1m,
                                                         float* __restrict__ sout) {
    extern __shared__ float sm[];
    float* xT = sm;              // [128][XS]
    float* sb = xT + 128 * XS;   // [128]

    const int tid = threadIdx.x;
    const int e0  = blockIdx.x * 128;

    const float* inb = state + (size_t)e0 * 128;
    for (int idx = tid; idx < 128 * 128; idx += 256) {
        int m = idx >> 7, k = idx & 127;
        xT[k * XS + m] = inb[idx];
    }
    if (tid < 128) sb[tid] = b1m[tid];
    __syncthreads();

    const int tr = tid >> 4, tc = tid & 15;
    float2 acc[8][4];
    ACC_CLEAR8(acc)

    const float4* wp1_ = reinterpret_cast<const float4*>(g_w1mT) + tc * 2;
#pragma unroll 4
    for (int k = 0; k < 128; ++k)
        GEMM_K_STEP8(xT + k * XS + tr * 8, wp1_ + k * 32, acc)

#pragma unroll
    for (int i = 0; i < 8; ++i)
#pragma unroll
        for (int j = 0; j < 4; ++j) {
            int col = tc * 8 + j * 2;
            acc[i][j].x = lsig(acc[i][j].x + sb[col]);
            acc[i][j].y = lsig(acc[i][j].y + sb[col + 1]);
        }
    __syncthreads();
#pragma unroll
    for (int i = 0; i < 8; ++i)
#pragma unroll
        for (int j = 0; j < 4; ++j) {
            xT[(tc * 8 + j * 2)     * XS + tr * 8 + i] = acc[i][j].x;
            xT[(tc * 8 + j * 2 + 1) * XS + tr * 8 + i] = acc[i][j].y;
        }
    __syncthreads();

    ACC_CLEAR8(acc)
    const float4* wp2_ = reinterpret_cast<const float4*>(g_w2mT) + tc * 2;
#pragma unroll 4
    for (int k = 0; k < 128; ++k)
        GEMM_K_STEP8(xT + k * XS + tr * 8, wp2_ + k * 32, acc)

#pragma unroll
    for (int i = 0; i < 8; ++i) {
        int row = e0 + tr * 8 + i;
        float r[8];
#pragma unroll
        for (int j = 0; j < 4; ++j) {
            r[j * 2]     = lsig(acc[i][j].x);
            r[j * 2 + 1] = lsig(acc[i][j].y);
        }
        float4* op = reinterpret_cast<float4*>(sout + (size_t)row * 128 + tc * 8);
        op[0] = make_float4(r[0], r[1], r[2], r[3]);
        op[1] = make_float4(r[4], r[5], r[6], r[7]);
    }
}

// ---------------------------------------------------------------------------
// Pure mask scan (overlapped with mem_mlp): builds both adjacency lists.
// ---------------------------------------------------------------------------
__global__ void __launch_bounds__(128) scan_lists_kernel(const float* __restrict__ mask) {
    const int n = blockIdx.x;
    const int slice = blockIdx.y;
    const int t = threadIdx.x;

    const float4* mrow = reinterpret_cast<const float4*>(mask + (size_t)n * E_TOT)
                         + slice * 1024;
    float4 mv[8];
#pragma unroll
    for (int q = 0; q < 8; ++q) mv[q] = __ldcs(&mrow[q * 128 + t]);

#pragma unroll
    for (int q = 0; q < 8; ++q) {
        int e0 = slice * 4096 + q * 512 + t * 4;
        float vals[4] = {mv[q].x, mv[q].y, mv[q].z, mv[q].w};
#pragma unroll
        for (int u = 0; u < 4; ++u) {
            if (vals[u] != 0.0f) {
                int e = e0 + u;
                int p = atomicAdd(&g_ncnt[n], 1);
                if (p < MAXNE) g_nlist[(size_t)n * MAXNE + p] = e;
                int q2 = atomicAdd(&g_edeg[e], 1);
                if (q2 < MAXED) g_enode[(size_t)e * MAXED + q2] = n;
            }
        }
    }
}

// ---------------------------------------------------------------------------
// Node gather: g_node[n][:] = sum of g_s rows (L2-bound).
// ---------------------------------------------------------------------------
__global__ void __launch_bounds__(128) node_sum_kernel() {
    const int n = blockIdx.x;
    const int t = threadIdx.x;
    int c = g_ncnt[n];
    if (c > MAXNE) c = MAXNE;
    const int* lst = g_nlist + (size_t)n * MAXNE;

    float a0 = 0.f, a1 = 0.f, a2 = 0.f, a3 = 0.f;
    int i = 0;
    for (; i + 4 <= c; i += 4) {
        int e0 = __ldg(lst + i), e1 = __ldg(lst + i + 1);
        int e2 = __ldg(lst + i + 2), e3 = __ldg(lst + i + 3);
        a0 += g_s[(size_t)e0 * 128 + t];
        a1 += g_s[(size_t)e1 * 128 + t];
        a2 += g_s[(size_t)e2 * 128 + t];
        a3 += g_s[(size_t)e3 * 128 + t];
    }
    for (; i < c; ++i) a0 += g_s[(size_t)__ldg(lst + i) * 128 + t];
    g_node[(size_t)n * 128 + t] = (a0 + a1) + (a2 + a3);
}

// ---------------------------------------------------------------------------
// Edge aggregation (was final_kernel's preamble): one thread per (edge, 32-slab).
// g_cat[e][:] = sum_{n in edge's nodes} g_node[n][:] - g_s[e][:]
// 131072 threads, unroll-2 over neighbors -> L2 BW bound.
// ---------------------------------------------------------------------------
__global__ void __launch_bounds__(256) agg_kernel() {
    int gid = blockIdx.x * 256 + threadIdx.x;
    int e  = gid >> 2;
    int kb = (gid & 3) << 5;
    int d = g_edeg[e];
    if (d > MAXED) d = MAXED;
    const int* nl = g_enode + (size_t)e * MAXED;

    float4 v[8];
    const float4* sp = reinterpret_cast<const float4*>(g_s + (size_t)e * 128 + kb);
#pragma unroll
    for (int q = 0; q < 8; ++q) {
        float4 f = sp[q];
        v[q] = make_float4(-f.x, -f.y, -f.z, -f.w);
    }
    int i = 0;
    for (; i + 2 <= d; i += 2) {
        int n0 = __ldg(nl + i), n1 = __ldg(nl + i + 1);
        const float4* p0 = reinterpret_cast<const float4*>(g_node + (size_t)n0 * 128 + kb);
        const float4* p1 = reinterpret_cast<const float4*>(g_node + (size_t)n1 * 128 + kb);
#pragma unroll
        for (int q = 0; q < 8; ++q) {
            float4 a = p0[q], b = p1[q];
            v[q].x += a.x + b.x; v[q].y += a.y + b.y;
            v[q].z += a.z + b.z; v[q].w += a.w + b.w;
        }
    }
    if (i < d) {
        int n0 = __ldg(nl + i);
        const float4* p0 = reinterpret_cast<const float4*>(g_node + (size_t)n0 * 128 + kb);
#pragma unroll
        for (int q = 0; q < 8; ++q) {
            float4 a = p0[q];
            v[q].x += a.x; v[q].y += a.y; v[q].z += a.z; v[q].w += a.w;
        }
    }
    float4* op = reinterpret_cast<float4*>(g_cat + (size_t)e * 128 + kb);
#pragma unroll
    for (int q = 0; q < 8; ++q) op[q] = v[q];
}

// ---------------------------------------------------------------------------
// Final MLP: out = ls( ls([g_cat, feature] @ W1a^T + b1a) @ W2a^T )
// Structurally identical to mem_mlp (coalesced load, two GEMMs), K=160.
// ---------------------------------------------------------------------------
__global__ void __launch_bounds__(256, 2) final_kernel(const float* __restrict__ feature,
                                                       const float* __restrict__ b1a,
                                                       float* __restrict__ out) {
    extern __shared__ float sm[];
    float* xT = sm;                   // [160][XS]; rows 0..127 recycled for hidden
    float* sb = xT + DCAT * XS;       // [128]

    const int tid = threadIdx.x;
    const int e0  = blockIdx.x * 128;

    const float* catb = g_cat + (size_t)e0 * 128;
    for (int idx = tid; idx < 128 * 128; idx += 256) {
        int m = idx >> 7, k = idx & 127;
        xT[k * XS + m] = catb[idx];
    }
    for (int idx = tid; idx < 128 * DF; idx += 256) {
        int m = idx >> 5, k = idx & 31;
        xT[(128 + k) * XS + m] = feature[(size_t)(e0 + m) * DF + k];
    }
    if (tid < 128) sb[tid] = b1a[tid];
    __syncthreads();

    const int tr = tid >> 4, tc = tid & 15;
    float2 acc[8][4];
    ACC_CLEAR8(acc)

    const float4* wp1_ = reinterpret_cast<const float4*>(g_w1aT) + tc * 2;
#pragma unroll 4
    for (int k = 0; k < DCAT; ++k)
        GEMM_K_STEP8(xT + k * XS + tr * 8, wp1_ + k * 32, acc)

#pragma unroll
    for (int i = 0; i < 8; ++i)
#pragma unroll
        for (int j = 0; j < 4; ++j) {
            int col = tc * 8 + j * 2;
            acc[i][j].x = lsig(acc[i][j].x + sb[col]);
            acc[i][j].y = lsig(acc[i][j].y + sb[col + 1]);
        }
    __syncthreads();
#pragma unroll
    for (int i = 0; i < 8; ++i)
#pragma unroll
        for (int j = 0; j < 4; ++j) {
            xT[(tc * 8 + j * 2)     * XS + tr * 8 + i] = acc[i][j].x;
            xT[(tc * 8 + j * 2 + 1) * XS + tr * 8 + i] = acc[i][j].y;
        }
    __syncthreads();

    ACC_CLEAR8(acc)
    const float4* wp2_ = reinterpret_cast<const float4*>(g_w2aT) + tc * 2;
#pragma unroll 4
    for (int k = 0; k < 128; ++k)
        GEMM_K_STEP8(xT + k * XS + tr * 8, wp2_ + k * 32, acc)

#pragma unroll
    for (int i = 0; i < 8; ++i) {
        int row = e0 + tr * 8 + i;
        float r[8];
#pragma unroll
        for (int j = 0; j < 4; ++j) {
            r[j * 2]     = lsig(acc[i][j].x);
            r[j * 2 + 1] = lsig(acc[i][j].y);
        }
        float4* op = reinterpret_cast<float4*>(out + (size_t)row * 128 + tc * 8);
        op[0] = make_float4(r[0], r[1], r[2], r[3]);
        op[1] = make_float4(r[4], r[5], r[6], r[7]);
    }
}

// ---------------------------------------------------------------------------
extern "C" void kernel_launch(void* const* d_in, const int* in_sizes, int n_in,
                              void* d_out, int out_size) {
    const float* state   = (const float*)d_in[0];
    const float* feature = (const float*)d_in[1];
    const float* mask    = (const float*)d_in[2];
    const float* W1m = (const float*)d_in[4];
    const float* b1m = (const float*)d_in[5];
    const float* W2m = (const float*)d_in[6];
    const float* W1a = (const float*)d_in[7];
    const float* b1a = (const float*)d_in[8];
    const float* W2a = (const float*)d_in[9];
    float* out = (float*)d_out;

    const int smem_mem   = (128 * XS + 128) * 4;   // ~68 KB
    const int smem_final = (DCAT * XS + 128) * 4;  // ~85 KB

    static cudaStream_t s_aux = nullptr;
    static cudaEvent_t ev_fork = nullptr, ev_scan = nullptr;
    if (s_aux == nullptr) {
        cudaStreamCreateWithFlags(&s_aux, cudaStreamNonBlocking);
        cudaEventCreateWithFlags(&ev_fork, cudaEventDisableTiming);
        cudaEventCreateWithFlags(&ev_scan, cudaEventDisableTiming);
        cudaFuncSetAttribute((const void*)mem_mlp_kernel,
                             cudaFuncAttributeMaxDynamicSharedMemorySize, smem_mem);
        cudaFuncSetAttribute((const void*)final_kernel,
                             cudaFuncAttributeMaxDynamicSharedMemorySize, smem_final);
    }

    void* p_s;
    cudaGetSymbolAddress(&p_s, g_s);

    zero_kernel<<<(E_TOT + 255) / 256, 256>>>();
    cudaEventRecord(ev_fork, 0);

    cudaStreamWaitEvent(s_aux, ev_fork, 0);
    scan_lists_kernel<<<dim3(N_NODES, 8), 128, 0, s_aux>>>(mask);
    cudaEventRecord(ev_scan, s_aux);

    wtrans_kernel<<<(69632 + 255) / 256, 256>>>(W1m, W2m, W1a, W2a);
    mem_mlp_kernel<<<E_TOT / 128, 256, smem_mem>>>(state, b1m, (float*)p_s);

    cudaStreamWaitEvent(0, ev_scan, 0);
    node_sum_kernel<<<N_NODES, 128>>>();
    agg_kernel<<<E_TOT * 4 / 256, 256>>>();
    final_kernel<<<E_TOT / 128, 256, smem_final>>>(feature, b1a, out);
}

// round 11
// speedup vs baseline: 1.0817x; 1.0817x over previous
#include <cuda_runtime.h>
#include <cstdint>

#define E_TOT   32768
#define N_NODES 2048
#define D       128
#define DF      32
#define DCAT    160
#define MAXED   64     // nodes per edge cap (mean ~10.2)
#define MAXNE   256    // edges per node cap (mean ~164)
#define XS      132    // x-tile stride: 16B-aligned rows for float4 LDS

// Scratch (__device__ globals: allocation-free rule)
__device__ float g_s [(size_t)E_TOT * D];
__device__ float g_node[(size_t)N_NODES * D];
__device__ int   g_edeg[E_TOT];
__device__ int   g_enode[(size_t)E_TOT * MAXED];
__device__ int   g_ncnt[N_NODES];
__device__ int   g_nlist[(size_t)N_NODES * MAXNE];
// Pre-transposed weights (k-major)
__device__ float g_w1mT[D * D];
__device__ float g_w2mT[D * D];
__device__ float g_w1aT[DCAT * D];
__device__ float g_w2aT[D * D];

__device__ __forceinline__ float lsig(float x) {
    return fminf(x, 0.0f) - log1pf(__expf(-fabsf(x)));
}

// Packed dual-FMA (sm_103a FFMA2)
__device__ __forceinline__ void ffma2(float2& d, const float2 a, const float2 b) {
    asm("fma.rn.f32x2 %0, %1, %2, %0;"
        : "+l"(*reinterpret_cast<unsigned long long*>(&d))
        : "l"(*reinterpret_cast<const unsigned long long*>(&a)),
          "l"(*reinterpret_cast<const unsigned long long*>(&b)));
}

__global__ void zero_kernel() {
    int i = blockIdx.x * blockDim.x + threadIdx.x;
    if (i < E_TOT) g_edeg[i] = 0;
    if (i < N_NODES) g_ncnt[i] = 0;
}

__global__ void wtrans_kernel(const float* __restrict__ W1m, const float* __restrict__ W2m,
                              const float* __restrict__ W1a, const float* __restrict__ W2a) {
    int i = blockIdx.x * blockDim.x + threadIdx.x;
    if (i < 16384) {
        int r = i >> 7, c = i & 127;
        g_w1mT[c * 128 + r] = W1m[i];
    } else if (i < 32768) {
        int j = i - 16384; int r = j >> 7, c = j & 127;
        g_w2mT[c * 128 + r] = W2m[j];
    } else if (i < 53248) {
        int j = i - 32768; int r = j / 160, c = j - r * 160;
        g_w1aT[c * 128 + r] = W1a[j];
    } else if (i < 69632) {
        int j = i - 53248; int r = j >> 7, c = j & 127;
        g_w2aT[c * 128 + r] = W2a[j];
    }
}

// ---------------------------------------------------------------------------
// 8x8 micro-tile GEMM step: 32B weights feed 64 MACs (0.5 B/MAC).
// ---------------------------------------------------------------------------
#define GEMM_K_STEP8(XK, WK, ACC)                                              \
    {                                                                          \
        const float4* _wkp = (WK);                                             \
        float4 _w0 = __ldg(_wkp), _w1 = __ldg(_wkp + 1);                       \
        const float4* _xp = reinterpret_cast<const float4*>(XK);               \
        float4 _xa = _xp[0], _xb = _xp[1];                                     \
        float2 _p0 = make_float2(_w0.x, _w0.y);                                \
        float2 _p1 = make_float2(_w0.z, _w0.w);                                \
        float2 _p2 = make_float2(_w1.x, _w1.y);                                \
        float2 _p3 = make_float2(_w1.z, _w1.w);                                \
        float _av[8] = {_xa.x, _xa.y, _xa.z, _xa.w, _xb.x, _xb.y, _xb.z, _xb.w};\
        _Pragma("unroll")                                                      \
        for (int _i = 0; _i < 8; ++_i) {                                       \
            float2 _ab = make_float2(_av[_i], _av[_i]);                        \
            ffma2(ACC[_i][0], _ab, _p0); ffma2(ACC[_i][1], _ab, _p1);          \
            ffma2(ACC[_i][2], _ab, _p2); ffma2(ACC[_i][3], _ab, _p3);          \
        }                                                                      \
    }

#define ACC_CLEAR8(ACC)                                                        \
    _Pragma("unroll") for (int i = 0; i < 8; ++i)                              \
    _Pragma("unroll") for (int j = 0; j < 4; ++j) ACC[i][j] = make_float2(0.f, 0.f);

// ---------------------------------------------------------------------------
// Fused memory MLP: g_s = ls( ls(state @ W1m^T + b1m) @ W2m^T )
// ---------------------------------------------------------------------------
__global__ void __launch_bounds__(256, 2) mem_mlp_kernel(const float* __restrict__ state,
                                                         const float* __restrict__ b1m,
                                                         float* __restrict__ sout) {
    extern __shared__ float sm[];
    float* xT = sm;              // [128][XS]
    float* sb = xT + 128 * XS;   // [128]

    const int tid = threadIdx.x;
    const int e0  = blockIdx.x * 128;

    const float* inb = state + (size_t)e0 * 128;
    for (int idx = tid; idx < 128 * 128; idx += 256) {
        int m = idx >> 7, k = idx & 127;
        xT[k * XS + m] = inb[idx];
    }
    if (tid < 128) sb[tid] = b1m[tid];
    __syncthreads();

    const int tr = tid >> 4, tc = tid & 15;
    float2 acc[8][4];
    ACC_CLEAR8(acc)

    const float4* wp1_ = reinterpret_cast<const float4*>(g_w1mT) + tc * 2;
#pragma unroll 4
    for (int k = 0; k < 128; ++k)
        GEMM_K_STEP8(xT + k * XS + tr * 8, wp1_ + k * 32, acc)

#pragma unroll
    for (int i = 0; i < 8; ++i)
#pragma unroll
        for (int j = 0; j < 4; ++j) {
            int col = tc * 8 + j * 2;
            acc[i][j].x = lsig(acc[i][j].x + sb[col]);
            acc[i][j].y = lsig(acc[i][j].y + sb[col + 1]);
        }
    __syncthreads();
#pragma unroll
    for (int i = 0; i < 8; ++i)
#pragma unroll
        for (int j = 0; j < 4; ++j) {
            xT[(tc * 8 + j * 2)     * XS + tr * 8 + i] = acc[i][j].x;
            xT[(tc * 8 + j * 2 + 1) * XS + tr * 8 + i] = acc[i][j].y;
        }
    __syncthreads();

    ACC_CLEAR8(acc)
    const float4* wp2_ = reinterpret_cast<const float4*>(g_w2mT) + tc * 2;
#pragma unroll 4
    for (int k = 0; k < 128; ++k)
        GEMM_K_STEP8(xT + k * XS + tr * 8, wp2_ + k * 32, acc)

#pragma unroll
    for (int i = 0; i < 8; ++i) {
        int row = e0 + tr * 8 + i;
        float r[8];
#pragma unroll
        for (int j = 0; j < 4; ++j) {
            r[j * 2]     = lsig(acc[i][j].x);
            r[j * 2 + 1] = lsig(acc[i][j].y);
        }
        float4* op = reinterpret_cast<float4*>(sout + (size_t)row * 128 + tc * 8);
        op[0] = make_float4(r[0], r[1], r[2], r[3]);
        op[1] = make_float4(r[4], r[5], r[6], r[7]);
    }
}

// ---------------------------------------------------------------------------
// Pure mask scan (overlapped with mem_mlp): builds both adjacency lists.
// ---------------------------------------------------------------------------
__global__ void __launch_bounds__(128) scan_lists_kernel(const float* __restrict__ mask) {
    const int n = blockIdx.x;
    const int slice = blockIdx.y;
    const int t = threadIdx.x;

    const float4* mrow = reinterpret_cast<const float4*>(mask + (size_t)n * E_TOT)
                         + slice * 1024;
    float4 mv[8];
#pragma unroll
    for (int q = 0; q < 8; ++q) mv[q] = __ldcs(&mrow[q * 128 + t]);

#pragma unroll
    for (int q = 0; q < 8; ++q) {
        int e0 = slice * 4096 + q * 512 + t * 4;
        float vals[4] = {mv[q].x, mv[q].y, mv[q].z, mv[q].w};
#pragma unroll
        for (int u = 0; u < 4; ++u) {
            if (vals[u] != 0.0f) {
                int e = e0 + u;
                int p = atomicAdd(&g_ncnt[n], 1);
                if (p < MAXNE) g_nlist[(size_t)n * MAXNE + p] = e;
                int q2 = atomicAdd(&g_edeg[e], 1);
                if (q2 < MAXED) g_enode[(size_t)e * MAXED + q2] = n;
            }
        }
    }
}

// ---------------------------------------------------------------------------
// Node gather: g_node[n][:] = sum of g_s rows. Unroll 8 -> 8 row-gathers in
// flight per thread (L2-BW bound instead of latency bound).
// ---------------------------------------------------------------------------
__global__ void __launch_bounds__(128) node_sum_kernel() {
    const int n = blockIdx.x;
    const int t = threadIdx.x;
    int c = g_ncnt[n];
    if (c > MAXNE) c = MAXNE;
    const int* lst = g_nlist + (size_t)n * MAXNE;

    float a0 = 0.f, a1 = 0.f, a2 = 0.f, a3 = 0.f;
    float a4 = 0.f, a5 = 0.f, a6 = 0.f, a7 = 0.f;
    int i = 0;
    for (; i + 8 <= c; i += 8) {
        int e0 = __ldg(lst + i),     e1 = __ldg(lst + i + 1);
        int e2 = __ldg(lst + i + 2), e3 = __ldg(lst + i + 3);
        int e4 = __ldg(lst + i + 4), e5 = __ldg(lst + i + 5);
        int e6 = __ldg(lst + i + 6), e7 = __ldg(lst + i + 7);
        a0 += g_s[(size_t)e0 * 128 + t];
        a1 += g_s[(size_t)e1 * 128 + t];
        a2 += g_s[(size_t)e2 * 128 + t];
        a3 += g_s[(size_t)e3 * 128 + t];
        a4 += g_s[(size_t)e4 * 128 + t];
        a5 += g_s[(size_t)e5 * 128 + t];
        a6 += g_s[(size_t)e6 * 128 + t];
        a7 += g_s[(size_t)e7 * 128 + t];
    }
    for (; i < c; ++i) a0 += g_s[(size_t)__ldg(lst + i) * 128 + t];
    g_node[(size_t)n * 128 + t] = ((a0 + a1) + (a2 + a3)) + ((a4 + a5) + (a6 + a7));
}

// ---------------------------------------------------------------------------
// Fused final stage: agg built in-block (2 threads/edge, 2 halves, neighbor
// unroll-2 for 16 L2 loads in flight), then two GEMMs. (R9 structure.)
// ---------------------------------------------------------------------------
__global__ void __launch_bounds__(256, 2) final_kernel(const float* __restrict__ feature,
                                                       const float* __restrict__ b1a,
                                                       float* __restrict__ out) {
    extern __shared__ float sm[];
    float* xT = sm;                   // [160][XS]; rows 0..127 recycled for hidden
    float* sb = xT + DCAT * XS;       // [128]

    const int tid = threadIdx.x;
    const int e0  = blockIdx.x * 128;

    // agg: 2 threads per edge; each covers 64 dims in two 32-dim passes
    {
        int m   = tid >> 1;
        int kb0 = (tid & 1) << 6;
        int e   = e0 + m;
        int d = g_edeg[e];
        if (d > MAXED) d = MAXED;
        const int* nl = g_enode + (size_t)e * MAXED;
#pragma unroll
        for (int half = 0; half < 2; ++half) {
            int kb = kb0 + half * 32;
            float4 v[8];
            const float4* sp = reinterpret_cast<const float4*>(g_s + (size_t)e * 128 + kb);
#pragma unroll
            for (int q = 0; q < 8; ++q) {
                float4 f = sp[q];
                v[q] = make_float4(-f.x, -f.y, -f.z, -f.w);
            }
            int i = 0;
            for (; i + 2 <= d; i += 2) {
                int n0 = __ldg(nl + i), n1 = __ldg(nl + i + 1);
                const float4* p0 = reinterpret_cast<const float4*>(g_node + (size_t)n0 * 128 + kb);
                const float4* p1 = reinterpret_cast<const float4*>(g_node + (size_t)n1 * 128 + kb);
#pragma unroll
                for (int q = 0; q < 8; ++q) {
                    float4 a = p0[q], b = p1[q];
                    v[q].x += a.x + b.x; v[q].y += a.y + b.y;
                    v[q].z += a.z + b.z; v[q].w += a.w + b.w;
                }
            }
            if (i < d) {
                int n0 = __ldg(nl + i);
                const float4* p0 = reinterpret_cast<const float4*>(g_node + (size_t)n0 * 128 + kb);
#pragma unroll
                for (int q = 0; q < 8; ++q) {
                    float4 a = p0[q];
                    v[q].x += a.x; v[q].y += a.y; v[q].z += a.z; v[q].w += a.w;
                }
            }
#pragma unroll
            for (int q = 0; q < 8; ++q) {
                xT[(kb + q * 4 + 0) * XS + m] = v[q].x;
                xT[(kb + q * 4 + 1) * XS + m] = v[q].y;
                xT[(kb + q * 4 + 2) * XS + m] = v[q].z;
                xT[(kb + q * 4 + 3) * XS + m] = v[q].w;
            }
        }
    }
    for (int idx = tid; idx < 128 * DF; idx += 256) {
        int m = idx >> 5, k = idx & 31;
        xT[(128 + k) * XS + m] = feature[(size_t)(e0 + m) * DF + k];
    }
    if (tid < 128) sb[tid] = b1a[tid];
    __syncthreads();

    const int tr = tid >> 4, tc = tid & 15;
    float2 acc[8][4];
    ACC_CLEAR8(acc)

    const float4* wp1_ = reinterpret_cast<const float4*>(g_w1aT) + tc * 2;
#pragma unroll 4
    for (int k = 0; k < DCAT; ++k)
        GEMM_K_STEP8(xT + k * XS + tr * 8, wp1_ + k * 32, acc)

#pragma unroll
    for (int i = 0; i < 8; ++i)
#pragma unroll
        for (int j = 0; j < 4; ++j) {
            int col = tc * 8 + j * 2;
            acc[i][j].x = lsig(acc[i][j].x + sb[col]);
            acc[i][j].y = lsig(acc[i][j].y + sb[col + 1]);
        }
    __syncthreads();
#pragma unroll
    for (int i = 0; i < 8; ++i)
#pragma unroll
        for (int j = 0; j < 4; ++j) {
            xT[(tc * 8 + j * 2)     * XS + tr * 8 + i] = acc[i][j].x;
            xT[(tc * 8 + j * 2 + 1) * XS + tr * 8 + i] = acc[i][j].y;
        }
    __syncthreads();

    ACC_CLEAR8(acc)
    const float4* wp2_ = reinterpret_cast<const float4*>(g_w2aT) + tc * 2;
#pragma unroll 4
    for (int k = 0; k < 128; ++k)
        GEMM_K_STEP8(xT + k * XS + tr * 8, wp2_ + k * 32, acc)

#pragma unroll
    for (int i = 0; i < 8; ++i) {
        int row = e0 + tr * 8 + i;
        float r[8];
#pragma unroll
        for (int j = 0; j < 4; ++j) {
            r[j * 2]     = lsig(acc[i][j].x);
            r[j * 2 + 1] = lsig(acc[i][j].y);
        }
        float4* op = reinterpret_cast<float4*>(out + (size_t)row * 128 + tc * 8);
        op[0] = make_float4(r[0], r[1], r[2], r[3]);
        op[1] = make_float4(r[4], r[5], r[6], r[7]);
    }
}

// ---------------------------------------------------------------------------
extern "C" void kernel_launch(void* const* d_in, const int* in_sizes, int n_in,
                              void* d_out, int out_size) {
    const float* state   = (const float*)d_in[0];
    const float* feature = (const float*)d_in[1];
    const float* mask    = (const float*)d_in[2];
    const float* W1m = (const float*)d_in[4];
    const float* b1m = (const float*)d_in[5];
    const float* W2m = (const float*)d_in[6];
    const float* W1a = (const float*)d_in[7];
    const float* b1a = (const float*)d_in[8];
    const float* W2a = (const float*)d_in[9];
    float* out = (float*)d_out;

    const int smem_mem   = (128 * XS + 128) * 4;   // ~68 KB
    const int smem_final = (DCAT * XS + 128) * 4;  // ~85 KB

    static cudaStream_t s_aux = nullptr;
    static cudaEvent_t ev_fork = nullptr, ev_scan = nullptr;
    if (s_aux == nullptr) {
        cudaStreamCreateWithFlags(&s_aux, cudaStreamNonBlocking);
        cudaEventCreateWithFlags(&ev_fork, cudaEventDisableTiming);
        cudaEventCreateWithFlags(&ev_scan, cudaEventDisableTiming);
        cudaFuncSetAttribute((const void*)mem_mlp_kernel,
                             cudaFuncAttributeMaxDynamicSharedMemorySize, smem_mem);
        cudaFuncSetAttribute((const void*)final_kernel,
                             cudaFuncAttributeMaxDynamicSharedMemorySize, smem_final);
    }

    void* p_s;
    cudaGetSymbolAddress(&p_s, g_s);

    zero_kernel<<<(E_TOT + 255) / 256, 256>>>();
    cudaEventRecord(ev_fork, 0);

    cudaStreamWaitEvent(s_aux, ev_fork, 0);
    scan_lists_kernel<<<dim3(N_NODES, 8), 128, 0, s_aux>>>(mask);
    cudaEventRecord(ev_scan, s_aux);

    wtrans_kernel<<<(69632 + 255) / 256, 256>>>(W1m, W2m, W1a, W2a);
    mem_mlp_kernel<<<E_TOT / 128, 256, smem_mem>>>(state, b1m, (float*)p_s);

    cudaStreamWaitEvent(0, ev_scan, 0);
    node_sum_kernel<<<N_NODES, 128>>>();
    final_kernel<<<E_TOT / 128, 256, smem_final>>>(feature, b1a, out);
}

// round 13
// speedup vs baseline: 1.2078x; 1.1166x over previous
#include <cuda_runtime.h>
#include <cuda_bf16.h>
#include <cstdint>

#define E_TOT   32768
#define N_NODES 2048
#define D       128
#define DF      32
#define MAXED   64
#define MAXNE   256

// smem byte strides per matrix row (bf16): pad so ldmatrix rows are conflict-free
#define SA_MM   272   // 136 bf16 (K=128 kernels)
#define SA_FN   336   // 168 bf16 (K=160 kernel)

// mem_mlp smem layout (bytes)
#define MA_HI 0
#define MA_LO 34816
#define MW_HI 69632
#define MW_LO 104448
#define MM_SMEM 139264
// final smem layout
#define FA_HI 0
#define FA_LO 43008
#define FW_HI 86016
#define FW_LO 129024
#define FN_SMEM 172032

// ---------------- scratch (__device__ globals) ----------------
__device__ float g_s [(size_t)E_TOT * D];
__device__ float g_node[(size_t)N_NODES * D];
__device__ int   g_edeg[E_TOT];
__device__ int   g_enode[(size_t)E_TOT * MAXED];
__device__ int   g_ncnt[N_NODES];
__device__ int   g_nlist[(size_t)N_NODES * MAXNE];
// pre-split bf16 weights, DENSE ORIGINAL [n][k] layout (= col-major B for mma row.col)
__device__ __nv_bfloat16 g_bw1m_hi[16384], g_bw1m_lo[16384];
__device__ __nv_bfloat16 g_bw2m_hi[16384], g_bw2m_lo[16384];
__device__ __nv_bfloat16 g_bw1a_hi[20480], g_bw1a_lo[20480];
__device__ __nv_bfloat16 g_bw2a_hi[16384], g_bw2a_lo[16384];

__device__ __forceinline__ float lsig(float x) {
    return fminf(x, 0.0f) - log1pf(__expf(-fabsf(x)));
}
__device__ __forceinline__ void split_bf16(float x, __nv_bfloat16& h, __nv_bfloat16& l) {
    h = __float2bfloat16(x);
    l = __float2bfloat16(x - __bfloat162float(h));
}
__device__ __forceinline__ uint32_t pack2(__nv_bfloat16 a, __nv_bfloat16 b) {
    __nv_bfloat162 t(a, b);
    return *reinterpret_cast<uint32_t*>(&t);
}
__device__ __forceinline__ uint32_t smem_to_u32(const void* p) {
    uint32_t a;
    asm("{ .reg .u64 t; cvta.to.shared.u64 t, %1; cvt.u32.u64 %0, t; }" : "=r"(a) : "l"(p));
    return a;
}
__device__ __forceinline__ void ldsm4(uint32_t a, uint32_t* r) {
    asm volatile("ldmatrix.sync.aligned.m8n8.x4.shared.b16 {%0,%1,%2,%3}, [%4];"
                 : "=r"(r[0]), "=r"(r[1]), "=r"(r[2]), "=r"(r[3]) : "r"(a));
}
__device__ __forceinline__ void mma16816(float* c, const uint32_t* a, uint32_t b0, uint32_t b1) {
    asm volatile("mma.sync.aligned.m16n8k16.row.col.f32.bf16.bf16.f32 "
                 "{%0,%1,%2,%3}, {%4,%5,%6,%7}, {%8,%9}, {%0,%1,%2,%3};"
                 : "+f"(c[0]), "+f"(c[1]), "+f"(c[2]), "+f"(c[3])
                 : "r"(a[0]), "r"(a[1]), "r"(a[2]), "r"(a[3]), "r"(b0), "r"(b1));
}

// ---------------------------------------------------------------------------
// 3-pass split-bf16 warp GEMM: c[2][8][4] covers 32 rows x 64 cols.
// A: row-major [M][K] bf16 smem (hi/lo). W: [N][K] bf16 smem (hi/lo) = col-major B.
// ---------------------------------------------------------------------------
template<int KS, int SAB>
__device__ __forceinline__ void mma_3pass(uint32_t aHi, uint32_t aLo,
                                          uint32_t wHi, uint32_t wLo,
                                          int lane, int m0, int n0,
                                          float c[2][8][4]) {
#pragma unroll
    for (int mt = 0; mt < 2; ++mt)
#pragma unroll
        for (int nt = 0; nt < 8; ++nt)
#pragma unroll
            for (int q = 0; q < 4; ++q) c[mt][nt][q] = 0.f;

    // ldmatrix per-lane base offsets (bytes)
    const uint32_t aOff = (uint32_t)((m0 + (lane & 15)) * SAB + ((lane >> 4) << 4));
    const uint32_t bOff = (uint32_t)((n0 + (lane & 7) + ((lane >> 4) << 3)) * SAB
                                     + (((lane >> 3) & 1) << 4));
#pragma unroll 1
    for (int pass = 0; pass < 3; ++pass) {
        const uint32_t ab = (pass == 2 ? aLo : aHi) + aOff;
        const uint32_t wb = (pass == 1 ? wLo : wHi) + bOff;
#pragma unroll
        for (int ks = 0; ks < KS; ++ks) {
            uint32_t av[2][4], bv[4][4];
            ldsm4(ab + ks * 32, av[0]);
            ldsm4(ab + 16 * SAB + ks * 32, av[1]);
#pragma unroll
            for (int nt2 = 0; nt2 < 4; ++nt2)
                ldsm4(wb + nt2 * 16 * SAB + ks * 32, bv[nt2]);
#pragma unroll
            for (int mt = 0; mt < 2; ++mt)
#pragma unroll
                for (int nt = 0; nt < 8; ++nt)
                    mma16816(c[mt][nt], av[mt],
                             bv[nt >> 1][(nt & 1) * 2], bv[nt >> 1][(nt & 1) * 2 + 1]);
        }
    }
}

// epilogue: h = lsig(c + bias) split-stored into smem A (hi/lo)
template<int SAB>
__device__ __forceinline__ void epi_to_smem(char* smc, int A_HI, int A_LO,
                                            int lane, int m0, int n0,
                                            float c[2][8][4], const float* bias) {
#pragma unroll
    for (int mt = 0; mt < 2; ++mt)
#pragma unroll
        for (int nt = 0; nt < 8; ++nt) {
            int col = n0 + nt * 8 + (lane & 3) * 2;
            int row = m0 + mt * 16 + (lane >> 2);
            float bc0 = __ldg(bias + col), bc1 = __ldg(bias + col + 1);
            __nv_bfloat16 h0, l0, h1, l1;
            float z0 = lsig(c[mt][nt][0] + bc0), z1 = lsig(c[mt][nt][1] + bc1);
            split_bf16(z0, h0, l0); split_bf16(z1, h1, l1);
            *(uint32_t*)(smc + A_HI + row * SAB + col * 2) = pack2(h0, h1);
            *(uint32_t*)(smc + A_LO + row * SAB + col * 2) = pack2(l0, l1);
            float z2 = lsig(c[mt][nt][2] + bc0), z3 = lsig(c[mt][nt][3] + bc1);
            split_bf16(z2, h0, l0); split_bf16(z3, h1, l1);
            *(uint32_t*)(smc + A_HI + (row + 8) * SAB + col * 2) = pack2(h0, h1);
            *(uint32_t*)(smc + A_LO + (row + 8) * SAB + col * 2) = pack2(l0, l1);
        }
}

// epilogue: out = lsig(c) to gmem (row-major 128 cols)
__device__ __forceinline__ void epi_to_gmem(float* outb, int lane, int m0, int n0,
                                            float c[2][8][4]) {
#pragma unroll
    for (int mt = 0; mt < 2; ++mt)
#pragma unroll
        for (int nt = 0; nt < 8; ++nt) {
            int col = n0 + nt * 8 + (lane & 3) * 2;
            int row = m0 + mt * 16 + (lane >> 2);
            *reinterpret_cast<float2*>(outb + (size_t)row * 128 + col) =
                make_float2(lsig(c[mt][nt][0]), lsig(c[mt][nt][1]));
            *reinterpret_cast<float2*>(outb + (size_t)(row + 8) * 128 + col) =
                make_float2(lsig(c[mt][nt][2]), lsig(c[mt][nt][3]));
        }
}

// ---------------- small kernels ----------------
__global__ void zero_kernel() {
    int i = blockIdx.x * blockDim.x + threadIdx.x;
    if (i < E_TOT) g_edeg[i] = 0;
    if (i < N_NODES) g_ncnt[i] = 0;
}

__global__ void wsplit_kernel(const float* __restrict__ W1m, const float* __restrict__ W2m,
                              const float* __restrict__ W1a, const float* __restrict__ W2a) {
    int i = blockIdx.x * blockDim.x + threadIdx.x;
    __nv_bfloat16 h, l;
    if (i < 16384) {
        split_bf16(W1m[i], h, l); g_bw1m_hi[i] = h; g_bw1m_lo[i] = l;
    } else if (i < 32768) {
        int j = i - 16384; split_bf16(W2m[j], h, l); g_bw2m_hi[j] = h; g_bw2m_lo[j] = l;
    } else if (i < 53248) {
        int j = i - 32768; split_bf16(W1a[j], h, l); g_bw1a_hi[j] = h; g_bw1a_lo[j] = l;
    } else if (i < 69632) {
        int j = i - 53248; split_bf16(W2a[j], h, l); g_bw2a_hi[j] = h; g_bw2a_lo[j] = l;
    }
}

__global__ void __launch_bounds__(128) scan_lists_kernel(const float* __restrict__ mask) {
    const int n = blockIdx.x, slice = blockIdx.y, t = threadIdx.x;
    const float4* mrow = reinterpret_cast<const float4*>(mask + (size_t)n * E_TOT) + slice * 1024;
    float4 mv[8];
#pragma unroll
    for (int q = 0; q < 8; ++q) mv[q] = __ldcs(&mrow[q * 128 + t]);
#pragma unroll
    for (int q = 0; q < 8; ++q) {
        int e0 = slice * 4096 + q * 512 + t * 4;
        float vals[4] = {mv[q].x, mv[q].y, mv[q].z, mv[q].w};
#pragma unroll
        for (int u = 0; u < 4; ++u) {
            if (vals[u] != 0.0f) {
                int e = e0 + u;
                int p = atomicAdd(&g_ncnt[n], 1);
                if (p < MAXNE) g_nlist[(size_t)n * MAXNE + p] = e;
                int q2 = atomicAdd(&g_edeg[e], 1);
                if (q2 < MAXED) g_enode[(size_t)e * MAXED + q2] = n;
            }
        }
    }
}

__global__ void __launch_bounds__(128) node_sum_kernel() {
    const int n = blockIdx.x, t = threadIdx.x;
    int c = g_ncnt[n];
    if (c > MAXNE) c = MAXNE;
    const int* lst = g_nlist + (size_t)n * MAXNE;
    float a0 = 0.f, a1 = 0.f, a2 = 0.f, a3 = 0.f, a4 = 0.f, a5 = 0.f, a6 = 0.f, a7 = 0.f;
    int i = 0;
    for (; i + 8 <= c; i += 8) {
        a0 += g_s[(size_t)__ldg(lst + i)     * 128 + t];
        a1 += g_s[(size_t)__ldg(lst + i + 1) * 128 + t];
        a2 += g_s[(size_t)__ldg(lst + i + 2) * 128 + t];
        a3 += g_s[(size_t)__ldg(lst + i + 3) * 128 + t];
        a4 += g_s[(size_t)__ldg(lst + i + 4) * 128 + t];
        a5 += g_s[(size_t)__ldg(lst + i + 5) * 128 + t];
        a6 += g_s[(size_t)__ldg(lst + i + 6) * 128 + t];
        a7 += g_s[(size_t)__ldg(lst + i + 7) * 128 + t];
    }
    for (; i < c; ++i) a0 += g_s[(size_t)__ldg(lst + i) * 128 + t];
    g_node[(size_t)n * 128 + t] = ((a0 + a1) + (a2 + a3)) + ((a4 + a5) + (a6 + a7));
}

// ---------------- HMMA memory MLP ----------------
__global__ void __launch_bounds__(256) mem_mlp_mma(const float* __restrict__ state,
                                                   const float* __restrict__ b1m,
                                                   float* __restrict__ sout) {
    extern __shared__ char smc[];
    const uint32_t sb = smem_to_u32(smc);
    const int tid = threadIdx.x, wid = tid >> 5, lane = tid & 31;
    const int e0 = blockIdx.x * 128;

    // stage x hi/lo
    for (int idx = tid; idx < 8192; idx += 256) {
        int m = idx >> 6, kp = idx & 63, kk = kp << 1;
        float2 f = reinterpret_cast<const float2*>(state + (size_t)(e0 + m) * 128)[kp];
        __nv_bfloat16 h0, l0, h1, l1;
        split_bf16(f.x, h0, l0); split_bf16(f.y, h1, l1);
        *(uint32_t*)(smc + MA_HI + m * SA_MM + kk * 2) = pack2(h0, h1);
        *(uint32_t*)(smc + MA_LO + m * SA_MM + kk * 2) = pack2(l0, l1);
    }
    // stage W1 (dense [n][k] -> padded rows)
    for (int idx = tid; idx < 2048; idx += 256) {
        int n = idx >> 4, kc = (idx & 15) << 3;
        *(float4*)(smc + MW_HI + n * SA_MM + kc * 2) = reinterpret_cast<const float4*>(g_bw1m_hi)[idx];
        *(float4*)(smc + MW_LO + n * SA_MM + kc * 2) = reinterpret_cast<const float4*>(g_bw1m_lo)[idx];
    }
    __syncthreads();

    const int m0 = (wid & 3) * 32, n0 = (wid >> 2) * 64;
    float c[2][8][4];
    mma_3pass<8, SA_MM>(sb + MA_HI, sb + MA_LO, sb + MW_HI, sb + MW_LO, lane, m0, n0, c);
    __syncthreads();
    epi_to_smem<SA_MM>(smc, MA_HI, MA_LO, lane, m0, n0, c, b1m);
    for (int idx = tid; idx < 2048; idx += 256) {
        int n = idx >> 4, kc = (idx & 15) << 3;
        *(float4*)(smc + MW_HI + n * SA_MM + kc * 2) = reinterpret_cast<const float4*>(g_bw2m_hi)[idx];
        *(float4*)(smc + MW_LO + n * SA_MM + kc * 2) = reinterpret_cast<const float4*>(g_bw2m_lo)[idx];
    }
    __syncthreads();
    mma_3pass<8, SA_MM>(sb + MA_HI, sb + MA_LO, sb + MW_HI, sb + MW_LO, lane, m0, n0, c);
    epi_to_gmem(sout + (size_t)e0 * 128, lane, m0, n0, c);
}

// ---------------- HMMA final stage ----------------
__global__ void __launch_bounds__(256) final_mma(const float* __restrict__ feature,
                                                 const float* __restrict__ b1a,
                                                 float* __restrict__ out) {
    extern __shared__ char smc[];
    const uint32_t sb = smem_to_u32(smc);
    const int tid = threadIdx.x, wid = tid >> 5, lane = tid & 31;
    const int e0 = blockIdx.x * 128;

    // agg preamble: 2 threads/edge, two 32-col passes; split-store into A (cols 0..127)
    {
        int m = tid >> 1, kb0 = (tid & 1) << 6;
        int e = e0 + m;
        int d = g_edeg[e];
        if (d > MAXED) d = MAXED;
        const int* nl = g_enode + (size_t)e * MAXED;
#pragma unroll
        for (int hlf = 0; hlf < 2; ++hlf) {
            int kb = kb0 + hlf * 32;
            float4 v[8];
            const float4* sp = reinterpret_cast<const float4*>(g_s + (size_t)e * 128 + kb);
#pragma unroll
            for (int q = 0; q < 8; ++q) {
                float4 f = sp[q];
                v[q] = make_float4(-f.x, -f.y, -f.z, -f.w);
            }
            int i = 0;
            for (; i + 2 <= d; i += 2) {
                int n0_ = __ldg(nl + i), n1_ = __ldg(nl + i + 1);
                const float4* p0 = reinterpret_cast<const float4*>(g_node + (size_t)n0_ * 128 + kb);
                const float4* p1 = reinterpret_cast<const float4*>(g_node + (size_t)n1_ * 128 + kb);
#pragma unroll
                for (int q = 0; q < 8; ++q) {
                    float4 a = p0[q], b = p1[q];
                    v[q].x += a.x + b.x; v[q].y += a.y + b.y;
                    v[q].z += a.z + b.z; v[q].w += a.w + b.w;
                }
            }
            if (i < d) {
                int n0_ = __ldg(nl + i);
                const float4* p0 = reinterpret_cast<const float4*>(g_node + (size_t)n0_ * 128 + kb);
#pragma unroll
                for (int q = 0; q < 8; ++q) {
                    float4 a = p0[q];
                    v[q].x += a.x; v[q].y += a.y; v[q].z += a.z; v[q].w += a.w;
                }
            }
#pragma unroll
            for (int q = 0; q < 8; ++q) {
                __nv_bfloat16 h0, l0, h1, l1;
                int col = kb + q * 4;
                split_bf16(v[q].x, h0, l0); split_bf16(v[q].y, h1, l1);
                *(uint32_t*)(smc + FA_HI + m * SA_FN + col * 2) = pack2(h0, h1);
                *(uint32_t*)(smc + FA_LO + m * SA_FN + col * 2) = pack2(l0, l1);
                split_bf16(v[q].z, h0, l0); split_bf16(v[q].w, h1, l1);
                *(uint32_t*)(smc + FA_HI + m * SA_FN + (col + 2) * 2) = pack2(h0, h1);
                *(uint32_t*)(smc + FA_LO + m * SA_FN + (col + 2) * 2) = pack2(l0, l1);
            }
        }
    }
    // feature cols 128..159
    for (int idx = tid; idx < 2048; idx += 256) {
        int m = idx >> 4, kp = idx & 15, kk = kp << 1;
        float2 f = reinterpret_cast<const float2*>(feature + (size_t)(e0 + m) * DF)[kp];
        __nv_bfloat16 h0, l0, h1, l1;
        split_bf16(f.x, h0, l0); split_bf16(f.y, h1, l1);
        *(uint32_t*)(smc + FA_HI + m * SA_FN + (128 + kk) * 2) = pack2(h0, h1);
        *(uint32_t*)(smc + FA_LO + m * SA_FN + (128 + kk) * 2) = pack2(l0, l1);
    }
    // W1a (dense [128][160])
    for (int idx = tid; idx < 2560; idx += 256) {
        int n = idx / 20, kc = (idx - n * 20) << 3;
        *(float4*)(smc + FW_HI + n * SA_FN + kc * 2) = reinterpret_cast<const float4*>(g_bw1a_hi)[idx];
        *(float4*)(smc + FW_LO + n * SA_FN + kc * 2) = reinterpret_cast<const float4*>(g_bw1a_lo)[idx];
    }
    __syncthreads();

    const int m0 = (wid & 3) * 32, n0 = (wid >> 2) * 64;
    float c[2][8][4];
    mma_3pass<10, SA_FN>(sb + FA_HI, sb + FA_LO, sb + FW_HI, sb + FW_LO, lane, m0, n0, c);
    __syncthreads();
    epi_to_smem<SA_FN>(smc, FA_HI, FA_LO, lane, m0, n0, c, b1a);
    for (int idx = tid; idx < 2048; idx += 256) {
        int n = idx >> 4, kc = (idx & 15) << 3;
        *(float4*)(smc + FW_HI + n * SA_FN + kc * 2) = reinterpret_cast<const float4*>(g_bw2a_hi)[idx];
        *(float4*)(smc + FW_LO + n * SA_FN + kc * 2) = reinterpret_cast<const float4*>(g_bw2a_lo)[idx];
    }
    __syncthreads();
    mma_3pass<8, SA_FN>(sb + FA_HI, sb + FA_LO, sb + FW_HI, sb + FW_LO, lane, m0, n0, c);
    epi_to_gmem(out + (size_t)e0 * 128, lane, m0, n0, c);
}

// ---------------------------------------------------------------------------
extern "C" void kernel_launch(void* const* d_in, const int* in_sizes, int n_in,
                              void* d_out, int out_size) {
    const float* state   = (const float*)d_in[0];
    const float* feature = (const float*)d_in[1];
    const float* mask    = (const float*)d_in[2];
    const float* W1m = (const float*)d_in[4];
    const float* b1m = (const float*)d_in[5];
    const float* W2m = (const float*)d_in[6];
    const float* W1a = (const float*)d_in[7];
    const float* b1a = (const float*)d_in[8];
    const float* W2a = (const float*)d_in[9];
    float* out = (float*)d_out;

    static cudaStream_t s_aux = nullptr;
    static cudaEvent_t ev_fork = nullptr, ev_scan = nullptr;
    if (s_aux == nullptr) {
        cudaStreamCreateWithFlags(&s_aux, cudaStreamNonBlocking);
        cudaEventCreateWithFlags(&ev_fork, cudaEventDisableTiming);
        cudaEventCreateWithFlags(&ev_scan, cudaEventDisableTiming);
        cudaFuncSetAttribute((const void*)mem_mlp_mma,
                             cudaFuncAttributeMaxDynamicSharedMemorySize, MM_SMEM);
        cudaFuncSetAttribute((const void*)final_mma,
                             cudaFuncAttributeMaxDynamicSharedMemorySize, FN_SMEM);
    }

    void* p_s;
    cudaGetSymbolAddress(&p_s, g_s);

    zero_kernel<<<(E_TOT + 255) / 256, 256>>>();
    cudaEventRecord(ev_fork, 0);

    cudaStreamWaitEvent(s_aux, ev_fork, 0);
    scan_lists_kernel<<<dim3(N_NODES, 8), 128, 0, s_aux>>>(mask);
    cudaEventRecord(ev_scan, s_aux);

    wsplit_kernel<<<(69632 + 255) / 256, 256>>>(W1m, W2m, W1a, W2a);
    mem_mlp_mma<<<E_TOT / 128, 256, MM_SMEM>>>(state, b1m, (float*)p_s);

    cudaStreamWaitEvent(0, ev_scan, 0);
    node_sum_kernel<<<N_NODES, 128>>>();
    final_mma<<<E_TOT / 128, 256, FN_SMEM>>>(feature, b1a, out);
}